// round 12
// baseline (speedup 1.0000x reference)
#include <cuda_runtime.h>
#include <cstdint>

#define NP 500000
#define NB 20000
#define NC 5000
#define NS 2000
#define NTOT 527000
#define NE 500000
#define EDIR (3 * NE * 2)
#define H 64
#define O 32
#define FIN 384

#define SCAN_SPAN 2048
#define NBLK_SCAN ((NTOT + SCAN_SPAN - 1) / SCAN_SPAN)

// ---------------- scratch ----------------------------------------------------
__device__ float g_x[(size_t)NTOT * H];
__device__ float g_h[(size_t)NTOT * H];
__device__ float g_agg[(size_t)NTOT * H];    // layer-1 mean of x (64-dim)
__device__ float g_y[(size_t)NTOT * O];      // y = relu(h) @ W2_l^T (32-dim)
__device__ float g_aggy[(size_t)NTOT * O];   // layer-2 mean of y (32-dim)
__device__ int   g_deg[NTOT];
__device__ int   g_rowstart[NTOT];
__device__ int   g_cursor[NTOT];
__device__ int   g_scaninc[NTOT];
__device__ int   g_blocksum[512];
__device__ int   g_adj[EDIR];

// ---------------- tf32 helpers ----------------------------------------------
__device__ __forceinline__ uint32_t f2tf(float x) {
    uint32_t r;
    asm("cvt.rna.tf32.f32 %0, %1;" : "=r"(r) : "f"(x));
    return r;
}
__device__ __forceinline__ void mma_tf32(float* d, uint32_t a0, uint32_t a1,
                                         uint32_t a2, uint32_t a3,
                                         uint32_t b0, uint32_t b1) {
    asm volatile(
        "mma.sync.aligned.m16n8k8.row.col.f32.tf32.tf32.f32 "
        "{%0,%1,%2,%3},{%4,%5,%6,%7},{%8,%9},{%0,%1,%2,%3};"
        : "+f"(d[0]), "+f"(d[1]), "+f"(d[2]), "+f"(d[3])
        : "r"(a0), "r"(a1), "r"(a2), "r"(a3), "r"(b0), "r"(b1));
}

// ---------------- CSR build ---------------------------------------------------
__global__ void __launch_bounds__(256) zero_deg() {
    int i = blockIdx.x * 256 + threadIdx.x;
    if (i < NTOT) g_deg[i] = 0;
}

__global__ void __launch_bounds__(256) hist_edges(
    const int* __restrict__ pb_src, const int* __restrict__ pb_dst,
    const int* __restrict__ pc_src, const int* __restrict__ pc_dst,
    const int* __restrict__ ps_src, const int* __restrict__ ps_dst) {
    int e = blockIdx.x * 256 + threadIdx.x;
    if (e >= 3 * NE) return;
    int t = e / NE, i = e - t * NE;
    const int* sp; const int* dp; int off;
    if (t == 0)      { sp = pb_src; dp = pb_dst; off = NP; }
    else if (t == 1) { sp = pc_src; dp = pc_dst; off = NP + NB; }
    else             { sp = ps_src; dp = ps_dst; off = NP + NB + NC; }
    int p = __ldg(sp + i);
    int o = __ldg(dp + i) + off;
    atomicAdd(&g_deg[p], 1);
    atomicAdd(&g_deg[o], 1);
}

__global__ void __launch_bounds__(256) scanA() {
    __shared__ int wsum[8];
    __shared__ int wpre[8];
    int tid = threadIdx.x, lane = tid & 31, wid = tid >> 5;
    int base = blockIdx.x * SCAN_SPAN + tid * 8;
    int v[8], run = 0;
#pragma unroll
    for (int t = 0; t < 8; t++) {
        int idx = base + t;
        int d = (idx < NTOT) ? g_deg[idx] : 0;
        run += d;
        v[t] = run;
    }
    int tot = run;
#pragma unroll
    for (int off = 1; off < 32; off <<= 1) {
        int n = __shfl_up_sync(0xffffffffu, tot, off);
        if (lane >= off) tot += n;
    }
    int wexcl = tot - run;
    if (lane == 31) wsum[wid] = tot;
    __syncthreads();
    if (tid < 8) {
        int s = wsum[tid];
        int r = s;
#pragma unroll
        for (int off = 1; off < 8; off <<= 1) {
            int n = __shfl_up_sync(0xffu, r, off);
            if (tid >= off) r += n;
        }
        wpre[tid] = r - s;
        if (tid == 7) g_blocksum[blockIdx.x] = r;
    }
    __syncthreads();
    int bexcl = wexcl + wpre[wid];
#pragma unroll
    for (int t = 0; t < 8; t++) {
        int idx = base + t;
        if (idx < NTOT) g_scaninc[idx] = v[t] + bexcl;
    }
}

__global__ void __launch_bounds__(512) scanB() {
    __shared__ int s[NBLK_SCAN];
    int tid = threadIdx.x;
    if (tid < NBLK_SCAN) s[tid] = g_blocksum[tid];
    __syncthreads();
    if (tid == 0) {
        int run = 0;
        for (int i = 0; i < NBLK_SCAN; i++) { int t = s[i]; s[i] = run; run += t; }
    }
    __syncthreads();
    if (tid < NBLK_SCAN) g_blocksum[tid] = s[tid];
}

__global__ void __launch_bounds__(256) scanC() {
    int i = blockIdx.x * 256 + threadIdx.x;
    if (i >= NTOT) return;
    int start = g_scaninc[i] + g_blocksum[i >> 11] - g_deg[i];
    g_rowstart[i] = start;
    g_cursor[i] = start;
}

__global__ void __launch_bounds__(256) fill_csr(
    const int* __restrict__ pb_src, const int* __restrict__ pb_dst,
    const int* __restrict__ pc_src, const int* __restrict__ pc_dst,
    const int* __restrict__ ps_src, const int* __restrict__ ps_dst) {
    int e = blockIdx.x * 256 + threadIdx.x;
    if (e >= 3 * NE) return;
    int t = e / NE, i = e - t * NE;
    const int* sp; const int* dp; int off;
    if (t == 0)      { sp = pb_src; dp = pb_dst; off = NP; }
    else if (t == 1) { sp = pc_src; dp = pc_dst; off = NP + NB; }
    else             { sp = ps_src; dp = ps_dst; off = NP + NB + NC; }
    int p = __ldg(sp + i);
    int o = __ldg(dp + i) + off;
    int pos = atomicAdd(&g_cursor[o], 1);
    g_adj[pos] = p;
    int pos2 = atomicAdd(&g_cursor[p], 1);
    g_adj[pos2] = o;
}

// ---------------- feature assembly --------------------------------------------
__global__ void __launch_bounds__(256) copy_emb(const float* __restrict__ eb,
                                                const float* __restrict__ ec,
                                                const float* __restrict__ es) {
    int i = blockIdx.x * 256 + threadIdx.x;
    const int tot = (NB + NC + NS) * H / 4;
    if (i >= tot) return;
    const int nb4 = NB * H / 4, nc4 = NC * H / 4;
    float4 v;
    if (i < nb4) v = reinterpret_cast<const float4*>(eb)[i];
    else if (i < nb4 + nc4) v = reinterpret_cast<const float4*>(ec)[i - nb4];
    else v = reinterpret_cast<const float4*>(es)[i - nb4 - nc4];
    reinterpret_cast<float4*>(g_x)[(size_t)NP * H / 4 + i] = v;
}

// ---------------- proj: relu(x_product @ W_proj^T + b) via tf32 HMMA ----------
__global__ void __launch_bounds__(256) proj_tc(const float* __restrict__ A,
                                               const float* __restrict__ W,
                                               const float* __restrict__ bias) {
    __shared__ uint32_t As[128][20];
    __shared__ uint32_t Ws[64][20];
    const int tid = threadIdx.x;
    const int m0 = blockIdx.x * 128;
    const int warp = tid >> 5, lane = tid & 31;
    const int g = lane >> 2, t = lane & 3;

    float acc[8][4];
#pragma unroll
    for (int j = 0; j < 8; j++)
#pragma unroll
        for (int c = 0; c < 4; c++) acc[j][c] = 0.f;

    for (int kb = 0; kb < FIN; kb += 16) {
#pragma unroll
        for (int q = 0; q < 2; q++) {
            int idx = tid + 256 * q;
            int row = idx >> 2, c4 = idx & 3;
            int rg = m0 + row; if (rg > NP - 1) rg = NP - 1;
            float4 v = *reinterpret_cast<const float4*>(A + (size_t)rg * FIN + kb + c4 * 4);
            uint4 u = make_uint4(f2tf(v.x), f2tf(v.y), f2tf(v.z), f2tf(v.w));
            *reinterpret_cast<uint4*>(&As[row][c4 * 4]) = u;
        }
        {
            int n = tid >> 2, c4 = tid & 3;
            float4 v = *reinterpret_cast<const float4*>(W + (size_t)n * FIN + kb + c4 * 4);
            uint4 u = make_uint4(f2tf(v.x), f2tf(v.y), f2tf(v.z), f2tf(v.w));
            *reinterpret_cast<uint4*>(&Ws[n][c4 * 4]) = u;
        }
        __syncthreads();
        const int r0 = warp * 16;
#pragma unroll
        for (int ks = 0; ks < 2; ks++) {
            int k0 = ks * 8;
            uint32_t a0 = As[r0 + g][k0 + t];
            uint32_t a1 = As[r0 + g + 8][k0 + t];
            uint32_t a2 = As[r0 + g][k0 + t + 4];
            uint32_t a3 = As[r0 + g + 8][k0 + t + 4];
#pragma unroll
            for (int j = 0; j < 8; j++) {
                uint32_t b0 = Ws[j * 8 + g][k0 + t];
                uint32_t b1 = Ws[j * 8 + g][k0 + t + 4];
                mma_tf32(acc[j], a0, a1, a2, a3, b0, b1);
            }
        }
        __syncthreads();
    }
#pragma unroll
    for (int j = 0; j < 8; j++) {
        int col = j * 8 + 2 * t;
        float b0 = bias[col], b1 = bias[col + 1];
        int r1 = m0 + warp * 16 + g;
        if (r1 < NP) {
            float2 o = make_float2(fmaxf(acc[j][0] + b0, 0.f), fmaxf(acc[j][1] + b1, 0.f));
            *reinterpret_cast<float2*>(g_x + (size_t)r1 * H + col) = o;
        }
        int r2 = r1 + 8;
        if (r2 < NP) {
            float2 o = make_float2(fmaxf(acc[j][2] + b0, 0.f), fmaxf(acc[j][3] + b1, 0.f));
            *reinterpret_cast<float2*>(g_x + (size_t)r2 * H + col) = o;
        }
    }
}

// ---------------- layer-1 aggregation: full-warp float2, 4 chains -------------
// Lane l owns feature columns (2l, 2l+1) for ALL neighbors -> no shuffle reduce.
// 4 independent rows in flight at the same register budget as the 2xfloat4 loop.
__global__ void __launch_bounds__(256) aggregate64() {
    int gw = (blockIdx.x * 256 + threadIdx.x) >> 5;
    if (gw >= NTOT) return;
    int node = NTOT - 1 - gw;     // heavy (high-id) rows first
    int lane = threadIdx.x & 31;
    int start = g_rowstart[node];
    int deg = g_deg[node];
    int f = lane * 2;
    float2 a0 = make_float2(0.f, 0.f), a1 = make_float2(0.f, 0.f);
    float2 a2 = make_float2(0.f, 0.f), a3 = make_float2(0.f, 0.f);
    int i = 0;
    for (; i + 3 < deg; i += 4) {
        int s0 = __ldg(g_adj + start + i);
        int s1 = __ldg(g_adj + start + i + 1);
        int s2 = __ldg(g_adj + start + i + 2);
        int s3 = __ldg(g_adj + start + i + 3);
        float2 v0 = *reinterpret_cast<const float2*>(g_x + (size_t)s0 * H + f);
        float2 v1 = *reinterpret_cast<const float2*>(g_x + (size_t)s1 * H + f);
        float2 v2 = *reinterpret_cast<const float2*>(g_x + (size_t)s2 * H + f);
        float2 v3 = *reinterpret_cast<const float2*>(g_x + (size_t)s3 * H + f);
        a0.x += v0.x; a0.y += v0.y;
        a1.x += v1.x; a1.y += v1.y;
        a2.x += v2.x; a2.y += v2.y;
        a3.x += v3.x; a3.y += v3.y;
    }
    if (i + 1 < deg) {
        int s0 = __ldg(g_adj + start + i);
        int s1 = __ldg(g_adj + start + i + 1);
        float2 v0 = *reinterpret_cast<const float2*>(g_x + (size_t)s0 * H + f);
        float2 v1 = *reinterpret_cast<const float2*>(g_x + (size_t)s1 * H + f);
        a0.x += v0.x; a0.y += v0.y;
        a1.x += v1.x; a1.y += v1.y;
        i += 2;
    }
    if (i < deg) {
        int s0 = __ldg(g_adj + start + i);
        float2 v0 = *reinterpret_cast<const float2*>(g_x + (size_t)s0 * H + f);
        a0.x += v0.x; a0.y += v0.y;
    }
    float inv = 1.f / fmaxf((float)deg, 1.f);
    float sx = (a0.x + a1.x) + (a2.x + a3.x);
    float sy = (a0.y + a1.y) + (a2.y + a3.y);
    *reinterpret_cast<float2*>(g_agg + (size_t)node * H + f) =
        make_float2(sx * inv, sy * inv);
}

// ---------------- layer-2 aggregation: full-warp float1, 4 chains -------------
// Lane l owns feature column l of the 32-dim y rows.
__global__ void __launch_bounds__(256) aggregate32() {
    int gw = (blockIdx.x * 256 + threadIdx.x) >> 5;
    if (gw >= NTOT) return;
    int node = NTOT - 1 - gw;
    int lane = threadIdx.x & 31;
    int start = g_rowstart[node];
    int deg = g_deg[node];
    float a0 = 0.f, a1 = 0.f, a2 = 0.f, a3 = 0.f;
    int i = 0;
    for (; i + 3 < deg; i += 4) {
        int s0 = __ldg(g_adj + start + i);
        int s1 = __ldg(g_adj + start + i + 1);
        int s2 = __ldg(g_adj + start + i + 2);
        int s3 = __ldg(g_adj + start + i + 3);
        a0 += __ldg(g_y + (size_t)s0 * O + lane);
        a1 += __ldg(g_y + (size_t)s1 * O + lane);
        a2 += __ldg(g_y + (size_t)s2 * O + lane);
        a3 += __ldg(g_y + (size_t)s3 * O + lane);
    }
    if (i + 1 < deg) {
        int s0 = __ldg(g_adj + start + i);
        int s1 = __ldg(g_adj + start + i + 1);
        a0 += __ldg(g_y + (size_t)s0 * O + lane);
        a1 += __ldg(g_y + (size_t)s1 * O + lane);
        i += 2;
    }
    if (i < deg) {
        int s0 = __ldg(g_adj + start + i);
        a0 += __ldg(g_y + (size_t)s0 * O + lane);
    }
    float inv = 1.f / fmaxf((float)deg, 1.f);
    g_aggy[(size_t)node * O + lane] = ((a0 + a1) + (a2 + a3)) * inv;
}

// ---------------- SAGE finalize layer 1 (exact round-5 body) ------------------
__global__ void __launch_bounds__(256) finalize1_tc(const float* __restrict__ Wr,
                                                    const float* __restrict__ Wl,
                                                    const float* __restrict__ bias) {
    __shared__ uint32_t As[128][20];
    __shared__ uint32_t Ws[64][20];
    const int tid = threadIdx.x;
    const int m0 = blockIdx.x * 128;
    const int warp = tid >> 5, lane = tid & 31;
    const int g = lane >> 2, t = lane & 3;

    float acc[8][4];
#pragma unroll
    for (int j = 0; j < 8; j++)
#pragma unroll
        for (int c = 0; c < 4; c++) acc[j][c] = 0.f;

    for (int kb = 0; kb < 2 * H; kb += 16) {
        const float* src = (kb < H) ? g_x : g_agg;
        const float* W = (kb < H) ? Wr : Wl;
        const int kcol = kb & (H - 1);
#pragma unroll
        for (int q = 0; q < 2; q++) {
            int idx = tid + 256 * q;
            int row = idx >> 2, c4 = idx & 3;
            int rg = m0 + row; if (rg > NTOT - 1) rg = NTOT - 1;
            float4 v = *reinterpret_cast<const float4*>(src + (size_t)rg * H + kcol + c4 * 4);
            uint4 u = make_uint4(f2tf(v.x), f2tf(v.y), f2tf(v.z), f2tf(v.w));
            *reinterpret_cast<uint4*>(&As[row][c4 * 4]) = u;
        }
        {
            int n = tid >> 2, c4 = tid & 3;
            float4 v = *reinterpret_cast<const float4*>(W + (size_t)n * H + kcol + c4 * 4);
            uint4 u = make_uint4(f2tf(v.x), f2tf(v.y), f2tf(v.z), f2tf(v.w));
            *reinterpret_cast<uint4*>(&Ws[n][c4 * 4]) = u;
        }
        __syncthreads();
        const int r0 = warp * 16;
#pragma unroll
        for (int ks = 0; ks < 2; ks++) {
            int k0 = ks * 8;
            uint32_t a0 = As[r0 + g][k0 + t];
            uint32_t a1 = As[r0 + g + 8][k0 + t];
            uint32_t a2 = As[r0 + g][k0 + t + 4];
            uint32_t a3 = As[r0 + g + 8][k0 + t + 4];
#pragma unroll
            for (int j = 0; j < 8; j++) {
                uint32_t b0 = Ws[j * 8 + g][k0 + t];
                uint32_t b1 = Ws[j * 8 + g][k0 + t + 4];
                mma_tf32(acc[j], a0, a1, a2, a3, b0, b1);
            }
        }
        __syncthreads();
    }
#pragma unroll
    for (int j = 0; j < 8; j++) {
        int col = j * 8 + 2 * t;
        float b0 = bias[col], b1 = bias[col + 1];
        int r1 = m0 + warp * 16 + g;
        if (r1 < NTOT) {
            float2 o = make_float2(fmaxf(acc[j][0] + b0, 0.f), fmaxf(acc[j][1] + b1, 0.f));
            *reinterpret_cast<float2*>(g_h + (size_t)r1 * H + col) = o;
        }
        int r2 = r1 + 8;
        if (r2 < NTOT) {
            float2 o = make_float2(fmaxf(acc[j][2] + b0, 0.f), fmaxf(acc[j][3] + b1, 0.f));
            *reinterpret_cast<float2*>(g_h + (size_t)r2 * H + col) = o;
        }
    }
}

// ---------------- y = h @ W2l^T (streaming GEMM, K=64, N=32) ------------------
__global__ void __launch_bounds__(256) y_tc(const float* __restrict__ W2l) {
    __shared__ uint32_t As[128][20];
    __shared__ uint32_t Ws[O][20];
    const int tid = threadIdx.x;
    const int m0 = blockIdx.x * 128;
    const int warp = tid >> 5, lane = tid & 31;
    const int g = lane >> 2, t = lane & 3;
    const int r0 = warp * 16;

    float acc[4][4];
#pragma unroll
    for (int j = 0; j < 4; j++)
#pragma unroll
        for (int c = 0; c < 4; c++) acc[j][c] = 0.f;

    for (int kb = 0; kb < H; kb += 16) {
#pragma unroll
        for (int q = 0; q < 2; q++) {
            int idx = tid + 256 * q;
            int row = idx >> 2, c4 = idx & 3;
            int rg = m0 + row; if (rg > NTOT - 1) rg = NTOT - 1;
            float4 v = *reinterpret_cast<const float4*>(g_h + (size_t)rg * H + kb + c4 * 4);
            uint4 u = make_uint4(f2tf(v.x), f2tf(v.y), f2tf(v.z), f2tf(v.w));
            *reinterpret_cast<uint4*>(&As[row][c4 * 4]) = u;
        }
        if (tid < O * 4) {
            int n = tid >> 2, c4 = tid & 3;
            float4 v = *reinterpret_cast<const float4*>(W2l + (size_t)n * H + kb + c4 * 4);
            uint4 u = make_uint4(f2tf(v.x), f2tf(v.y), f2tf(v.z), f2tf(v.w));
            *reinterpret_cast<uint4*>(&Ws[n][c4 * 4]) = u;
        }
        __syncthreads();
#pragma unroll
        for (int ks = 0; ks < 2; ks++) {
            int k0 = ks * 8;
            uint32_t a0 = As[r0 + g][k0 + t];
            uint32_t a1 = As[r0 + g + 8][k0 + t];
            uint32_t a2 = As[r0 + g][k0 + t + 4];
            uint32_t a3 = As[r0 + g + 8][k0 + t + 4];
#pragma unroll
            for (int j = 0; j < 4; j++) {
                uint32_t b0 = Ws[j * 8 + g][k0 + t];
                uint32_t b1 = Ws[j * 8 + g][k0 + t + 4];
                mma_tf32(acc[j], a0, a1, a2, a3, b0, b1);
            }
        }
        __syncthreads();
    }
#pragma unroll
    for (int j = 0; j < 4; j++) {
        int col = j * 8 + 2 * t;
        int r1 = m0 + r0 + g, r2 = r1 + 8;
        if (r1 < NTOT)
            *reinterpret_cast<float2*>(g_y + (size_t)r1 * O + col) =
                make_float2(acc[j][0], acc[j][1]);
        if (r2 < NTOT)
            *reinterpret_cast<float2*>(g_y + (size_t)r2 * O + col) =
                make_float2(acc[j][2], acc[j][3]);
    }
}

// ---------------- fin2: out = h@W2r^T + aggy + b2 (K=64, N=32) ----------------
__global__ void __launch_bounds__(256) fin2_tc(const float* __restrict__ W2r,
                                               const float* __restrict__ b2,
                                               float* __restrict__ out) {
    __shared__ uint32_t As[128][20];
    __shared__ uint32_t Ws[O][20];
    const int tid = threadIdx.x;
    const int m0 = blockIdx.x * 128;
    const int warp = tid >> 5, lane = tid & 31;
    const int g = lane >> 2, t = lane & 3;
    const int r0 = warp * 16;

    float acc[4][4];
#pragma unroll
    for (int j = 0; j < 4; j++)
#pragma unroll
        for (int c = 0; c < 4; c++) acc[j][c] = 0.f;

    for (int kb = 0; kb < H; kb += 16) {
#pragma unroll
        for (int q = 0; q < 2; q++) {
            int idx = tid + 256 * q;
            int row = idx >> 2, c4 = idx & 3;
            int rg = m0 + row; if (rg > NTOT - 1) rg = NTOT - 1;
            float4 v = *reinterpret_cast<const float4*>(g_h + (size_t)rg * H + kb + c4 * 4);
            uint4 u = make_uint4(f2tf(v.x), f2tf(v.y), f2tf(v.z), f2tf(v.w));
            *reinterpret_cast<uint4*>(&As[row][c4 * 4]) = u;
        }
        if (tid < O * 4) {
            int n = tid >> 2, c4 = tid & 3;
            float4 v = *reinterpret_cast<const float4*>(W2r + (size_t)n * H + kb + c4 * 4);
            uint4 u = make_uint4(f2tf(v.x), f2tf(v.y), f2tf(v.z), f2tf(v.w));
            *reinterpret_cast<uint4*>(&Ws[n][c4 * 4]) = u;
        }
        __syncthreads();
#pragma unroll
        for (int ks = 0; ks < 2; ks++) {
            int k0 = ks * 8;
            uint32_t a0 = As[r0 + g][k0 + t];
            uint32_t a1 = As[r0 + g + 8][k0 + t];
            uint32_t a2 = As[r0 + g][k0 + t + 4];
            uint32_t a3 = As[r0 + g + 8][k0 + t + 4];
#pragma unroll
            for (int j = 0; j < 4; j++) {
                uint32_t b0 = Ws[j * 8 + g][k0 + t];
                uint32_t b1 = Ws[j * 8 + g][k0 + t + 4];
                mma_tf32(acc[j], a0, a1, a2, a3, b0, b1);
            }
        }
        __syncthreads();
    }
#pragma unroll
    for (int j = 0; j < 4; j++) {
        int col = j * 8 + 2 * t;
        float b0 = b2[col], b1v = b2[col + 1];
        int r1 = m0 + r0 + g, r2 = r1 + 8;
        if (r1 < NTOT) {
            float2 ay = *reinterpret_cast<const float2*>(g_aggy + (size_t)r1 * O + col);
            *reinterpret_cast<float2*>(out + (size_t)r1 * O + col) =
                make_float2(acc[j][0] + b0 + ay.x, acc[j][1] + b1v + ay.y);
        }
        if (r2 < NTOT) {
            float2 ay = *reinterpret_cast<const float2*>(g_aggy + (size_t)r2 * O + col);
            *reinterpret_cast<float2*>(out + (size_t)r2 * O + col) =
                make_float2(acc[j][2] + b0 + ay.x, acc[j][3] + b1v + ay.y);
        }
    }
}

// ---------------- launch -------------------------------------------------------
extern "C" void kernel_launch(void* const* d_in, const int* in_sizes, int n_in,
                              void* d_out, int out_size) {
    const float* x_product = (const float*)d_in[0];
    const int* pb_src = (const int*)d_in[1];
    const int* pb_dst = (const int*)d_in[2];
    const int* pc_src = (const int*)d_in[3];
    const int* pc_dst = (const int*)d_in[4];
    const int* ps_src = (const int*)d_in[5];
    const int* ps_dst = (const int*)d_in[6];
    const float* W_proj = (const float*)d_in[7];
    const float* b_proj = (const float*)d_in[8];
    const float* emb_brand = (const float*)d_in[9];
    const float* emb_cat = (const float*)d_in[10];
    const float* emb_shop = (const float*)d_in[11];
    const float* W1_l = (const float*)d_in[12];
    const float* b1_l = (const float*)d_in[13];
    const float* W1_r = (const float*)d_in[14];
    const float* W2_l = (const float*)d_in[15];
    const float* b2_l = (const float*)d_in[16];
    const float* W2_r = (const float*)d_in[17];
    float* out = (float*)d_out;

    const int nodeBlocks = (NTOT + 255) / 256;
    const int edgeBlocks = (3 * NE + 255) / 256;
    const int aggBlocks = (NTOT * 32 + 255) / 256;
    const int gemmBlocks = (NTOT + 127) / 128;

    static cudaStream_t s2 = nullptr;
    static cudaEvent_t evFork = nullptr, evJoin = nullptr;
    if (!s2) {
        cudaStreamCreateWithFlags(&s2, cudaStreamNonBlocking);
        cudaEventCreateWithFlags(&evFork, cudaEventDisableTiming);
        cudaEventCreateWithFlags(&evJoin, cudaEventDisableTiming);
    }

    // fork: CSR build on s2, feature assembly on main (round-5 proven DAG)
    cudaEventRecord(evFork, 0);
    cudaStreamWaitEvent(s2, evFork, 0);

    zero_deg<<<nodeBlocks, 256, 0, s2>>>();
    hist_edges<<<edgeBlocks, 256, 0, s2>>>(pb_src, pb_dst, pc_src, pc_dst, ps_src, ps_dst);
    scanA<<<NBLK_SCAN, 256, 0, s2>>>();
    scanB<<<1, 512, 0, s2>>>();
    scanC<<<nodeBlocks, 256, 0, s2>>>();
    fill_csr<<<edgeBlocks, 256, 0, s2>>>(pb_src, pb_dst, pc_src, pc_dst, ps_src, ps_dst);
    cudaEventRecord(evJoin, s2);

    proj_tc<<<(NP + 127) / 128, 256>>>(x_product, W_proj, b_proj);
    copy_emb<<<((NB + NC + NS) * H / 4 + 255) / 256, 256>>>(emb_brand, emb_cat, emb_shop);

    cudaStreamWaitEvent(0, evJoin, 0);

    // --- layer 1 ---
    aggregate64<<<aggBlocks, 256>>>();
    finalize1_tc<<<gemmBlocks, 256>>>(W1_r, W1_l, b1_l);
    // --- y projection + layer 2 ---
    y_tc<<<gemmBlocks, 256>>>(W2_l);
    aggregate32<<<aggBlocks, 256>>>();
    fin2_tc<<<gemmBlocks, 256>>>(W2_r, b2_l, out);
}

// round 13
// speedup vs baseline: 1.0369x; 1.0369x over previous
#include <cuda_runtime.h>
#include <cstdint>

#define NP 500000
#define NB 20000
#define NC 5000
#define NS 2000
#define NTOT 527000
#define NE 500000
#define EDIR (3 * NE * 2)
#define H 64
#define O 32
#define FIN 384

#define SCAN_SPAN 2048
#define NBLK_SCAN ((NTOT + SCAN_SPAN - 1) / SCAN_SPAN)
#define PERS_BLOCKS 1184   // 148 SMs x 8 CTAs

// ---------------- scratch ----------------------------------------------------
__device__ float g_x[(size_t)NTOT * H];
__device__ float g_h[(size_t)NTOT * H];
__device__ float g_agg[(size_t)NTOT * H];    // layer-1 mean of x (64-dim)
__device__ float g_y[(size_t)NTOT * O];      // y = relu(h) @ W2_l^T (32-dim)
__device__ float g_aggy[(size_t)NTOT * O];   // layer-2 mean of y (32-dim)
__device__ int   g_deg[NTOT];
__device__ int   g_rowstart[NTOT];
__device__ int   g_cursor[NTOT];
__device__ int   g_scaninc[NTOT];
__device__ int   g_blocksum[512];
__device__ int   g_adj[EDIR];

// ---------------- tf32 helpers ----------------------------------------------
__device__ __forceinline__ uint32_t f2tf(float x) {
    uint32_t r;
    asm("cvt.rna.tf32.f32 %0, %1;" : "=r"(r) : "f"(x));
    return r;
}
__device__ __forceinline__ void mma_tf32(float* d, uint32_t a0, uint32_t a1,
                                         uint32_t a2, uint32_t a3,
                                         uint32_t b0, uint32_t b1) {
    asm volatile(
        "mma.sync.aligned.m16n8k8.row.col.f32.tf32.tf32.f32 "
        "{%0,%1,%2,%3},{%4,%5,%6,%7},{%8,%9},{%0,%1,%2,%3};"
        : "+f"(d[0]), "+f"(d[1]), "+f"(d[2]), "+f"(d[3])
        : "r"(a0), "r"(a1), "r"(a2), "r"(a3), "r"(b0), "r"(b1));
}

// ---------------- CSR build ---------------------------------------------------
__global__ void __launch_bounds__(256) zero_deg() {
    int i = blockIdx.x * 256 + threadIdx.x;
    if (i < NTOT) g_deg[i] = 0;
}

__global__ void __launch_bounds__(256) hist_edges(
    const int* __restrict__ pb_src, const int* __restrict__ pb_dst,
    const int* __restrict__ pc_src, const int* __restrict__ pc_dst,
    const int* __restrict__ ps_src, const int* __restrict__ ps_dst) {
    int e = blockIdx.x * 256 + threadIdx.x;
    if (e >= 3 * NE) return;
    int t = e / NE, i = e - t * NE;
    const int* sp; const int* dp; int off;
    if (t == 0)      { sp = pb_src; dp = pb_dst; off = NP; }
    else if (t == 1) { sp = pc_src; dp = pc_dst; off = NP + NB; }
    else             { sp = ps_src; dp = ps_dst; off = NP + NB + NC; }
    int p = __ldg(sp + i);
    int o = __ldg(dp + i) + off;
    atomicAdd(&g_deg[p], 1);
    atomicAdd(&g_deg[o], 1);
}

__global__ void __launch_bounds__(256) scanA() {
    __shared__ int wsum[8];
    __shared__ int wpre[8];
    int tid = threadIdx.x, lane = tid & 31, wid = tid >> 5;
    int base = blockIdx.x * SCAN_SPAN + tid * 8;
    int v[8], run = 0;
#pragma unroll
    for (int t = 0; t < 8; t++) {
        int idx = base + t;
        int d = (idx < NTOT) ? g_deg[idx] : 0;
        run += d;
        v[t] = run;
    }
    int tot = run;
#pragma unroll
    for (int off = 1; off < 32; off <<= 1) {
        int n = __shfl_up_sync(0xffffffffu, tot, off);
        if (lane >= off) tot += n;
    }
    int wexcl = tot - run;
    if (lane == 31) wsum[wid] = tot;
    __syncthreads();
    if (tid < 8) {
        int s = wsum[tid];
        int r = s;
#pragma unroll
        for (int off = 1; off < 8; off <<= 1) {
            int n = __shfl_up_sync(0xffu, r, off);
            if (tid >= off) r += n;
        }
        wpre[tid] = r - s;
        if (tid == 7) g_blocksum[blockIdx.x] = r;
    }
    __syncthreads();
    int bexcl = wexcl + wpre[wid];
#pragma unroll
    for (int t = 0; t < 8; t++) {
        int idx = base + t;
        if (idx < NTOT) g_scaninc[idx] = v[t] + bexcl;
    }
}

__global__ void __launch_bounds__(512) scanB() {
    __shared__ int s[NBLK_SCAN];
    int tid = threadIdx.x;
    if (tid < NBLK_SCAN) s[tid] = g_blocksum[tid];
    __syncthreads();
    if (tid == 0) {
        int run = 0;
        for (int i = 0; i < NBLK_SCAN; i++) { int t = s[i]; s[i] = run; run += t; }
    }
    __syncthreads();
    if (tid < NBLK_SCAN) g_blocksum[tid] = s[tid];
}

__global__ void __launch_bounds__(256) scanC() {
    int i = blockIdx.x * 256 + threadIdx.x;
    if (i >= NTOT) return;
    int start = g_scaninc[i] + g_blocksum[i >> 11] - g_deg[i];
    g_rowstart[i] = start;
    g_cursor[i] = start;
}

__global__ void __launch_bounds__(256) fill_csr(
    const int* __restrict__ pb_src, const int* __restrict__ pb_dst,
    const int* __restrict__ pc_src, const int* __restrict__ pc_dst,
    const int* __restrict__ ps_src, const int* __restrict__ ps_dst) {
    int e = blockIdx.x * 256 + threadIdx.x;
    if (e >= 3 * NE) return;
    int t = e / NE, i = e - t * NE;
    const int* sp; const int* dp; int off;
    if (t == 0)      { sp = pb_src; dp = pb_dst; off = NP; }
    else if (t == 1) { sp = pc_src; dp = pc_dst; off = NP + NB; }
    else             { sp = ps_src; dp = ps_dst; off = NP + NB + NC; }
    int p = __ldg(sp + i);
    int o = __ldg(dp + i) + off;
    int pos = atomicAdd(&g_cursor[o], 1);
    g_adj[pos] = p;
    int pos2 = atomicAdd(&g_cursor[p], 1);
    g_adj[pos2] = o;
}

// ---------------- feature assembly --------------------------------------------
__global__ void __launch_bounds__(256) copy_emb(const float* __restrict__ eb,
                                                const float* __restrict__ ec,
                                                const float* __restrict__ es) {
    int i = blockIdx.x * 256 + threadIdx.x;
    const int tot = (NB + NC + NS) * H / 4;
    if (i >= tot) return;
    const int nb4 = NB * H / 4, nc4 = NC * H / 4;
    float4 v;
    if (i < nb4) v = reinterpret_cast<const float4*>(eb)[i];
    else if (i < nb4 + nc4) v = reinterpret_cast<const float4*>(ec)[i - nb4];
    else v = reinterpret_cast<const float4*>(es)[i - nb4 - nc4];
    reinterpret_cast<float4*>(g_x)[(size_t)NP * H / 4 + i] = v;
}

// ---------------- proj: relu(x_product @ W_proj^T + b), register-prefetched ---
__global__ void __launch_bounds__(256) proj_tc(const float* __restrict__ A,
                                               const float* __restrict__ W,
                                               const float* __restrict__ bias) {
    __shared__ uint32_t As[128][20];
    __shared__ uint32_t Ws[64][20];
    const int tid = threadIdx.x;
    const int m0 = blockIdx.x * 128;
    const int warp = tid >> 5, lane = tid & 31;
    const int g = lane >> 2, t = lane & 3;

    const int arow = tid >> 2, ac4 = tid & 3;
    int arg0 = m0 + arow;        if (arg0 > NP - 1) arg0 = NP - 1;
    int arg1 = m0 + arow + 64;   if (arg1 > NP - 1) arg1 = NP - 1;
    const int wn = tid >> 2, wc4 = tid & 3;

    float acc[8][4];
#pragma unroll
    for (int j = 0; j < 8; j++)
#pragma unroll
        for (int c = 0; c < 4; c++) acc[j][c] = 0.f;

    float4 pa0 = *reinterpret_cast<const float4*>(A + (size_t)arg0 * FIN + ac4 * 4);
    float4 pa1 = *reinterpret_cast<const float4*>(A + (size_t)arg1 * FIN + ac4 * 4);
    float4 pw  = *reinterpret_cast<const float4*>(W + (size_t)wn * FIN + wc4 * 4);

    for (int kb = 0; kb < FIN; kb += 16) {
        *reinterpret_cast<uint4*>(&As[arow][ac4 * 4]) =
            make_uint4(f2tf(pa0.x), f2tf(pa0.y), f2tf(pa0.z), f2tf(pa0.w));
        *reinterpret_cast<uint4*>(&As[arow + 64][ac4 * 4]) =
            make_uint4(f2tf(pa1.x), f2tf(pa1.y), f2tf(pa1.z), f2tf(pa1.w));
        *reinterpret_cast<uint4*>(&Ws[wn][wc4 * 4]) =
            make_uint4(f2tf(pw.x), f2tf(pw.y), f2tf(pw.z), f2tf(pw.w));
        __syncthreads();
        if (kb + 16 < FIN) {
            pa0 = *reinterpret_cast<const float4*>(A + (size_t)arg0 * FIN + kb + 16 + ac4 * 4);
            pa1 = *reinterpret_cast<const float4*>(A + (size_t)arg1 * FIN + kb + 16 + ac4 * 4);
            pw  = *reinterpret_cast<const float4*>(W + (size_t)wn * FIN + kb + 16 + wc4 * 4);
        }
        const int r0 = warp * 16;
#pragma unroll
        for (int ks = 0; ks < 2; ks++) {
            int k0 = ks * 8;
            uint32_t a0 = As[r0 + g][k0 + t];
            uint32_t a1 = As[r0 + g + 8][k0 + t];
            uint32_t a2 = As[r0 + g][k0 + t + 4];
            uint32_t a3 = As[r0 + g + 8][k0 + t + 4];
#pragma unroll
            for (int j = 0; j < 8; j++) {
                uint32_t b0 = Ws[j * 8 + g][k0 + t];
                uint32_t b1 = Ws[j * 8 + g][k0 + t + 4];
                mma_tf32(acc[j], a0, a1, a2, a3, b0, b1);
            }
        }
        __syncthreads();
    }
#pragma unroll
    for (int j = 0; j < 8; j++) {
        int col = j * 8 + 2 * t;
        float b0 = bias[col], b1 = bias[col + 1];
        int r1 = m0 + warp * 16 + g;
        if (r1 < NP) {
            float2 o = make_float2(fmaxf(acc[j][0] + b0, 0.f), fmaxf(acc[j][1] + b1, 0.f));
            *reinterpret_cast<float2*>(g_x + (size_t)r1 * H + col) = o;
        }
        int r2 = r1 + 8;
        if (r2 < NP) {
            float2 o = make_float2(fmaxf(acc[j][2] + b0, 0.f), fmaxf(acc[j][3] + b1, 0.f));
            *reinterpret_cast<float2*>(g_x + (size_t)r2 * H + col) = o;
        }
    }
}

// ---------------- layer-1 aggregation: persistent grid-stride, float2 x4 ------
__global__ void __launch_bounds__(256) aggregate64() {
    const int nwarps = (int)gridDim.x * 8;
    int gw = (blockIdx.x * 256 + threadIdx.x) >> 5;
    int lane = threadIdx.x & 31;
    int f = lane * 2;
    for (int idx = gw; idx < NTOT; idx += nwarps) {
        int node = NTOT - 1 - idx;   // heavy (high-id) rows first
        int start = g_rowstart[node];
        int deg = g_deg[node];
        float2 a0 = make_float2(0.f, 0.f), a1 = make_float2(0.f, 0.f);
        float2 a2 = make_float2(0.f, 0.f), a3 = make_float2(0.f, 0.f);
        int i = 0;
        for (; i + 3 < deg; i += 4) {
            int s0 = __ldg(g_adj + start + i);
            int s1 = __ldg(g_adj + start + i + 1);
            int s2 = __ldg(g_adj + start + i + 2);
            int s3 = __ldg(g_adj + start + i + 3);
            float2 v0 = *reinterpret_cast<const float2*>(g_x + (size_t)s0 * H + f);
            float2 v1 = *reinterpret_cast<const float2*>(g_x + (size_t)s1 * H + f);
            float2 v2 = *reinterpret_cast<const float2*>(g_x + (size_t)s2 * H + f);
            float2 v3 = *reinterpret_cast<const float2*>(g_x + (size_t)s3 * H + f);
            a0.x += v0.x; a0.y += v0.y;
            a1.x += v1.x; a1.y += v1.y;
            a2.x += v2.x; a2.y += v2.y;
            a3.x += v3.x; a3.y += v3.y;
        }
        if (i + 1 < deg) {
            int s0 = __ldg(g_adj + start + i);
            int s1 = __ldg(g_adj + start + i + 1);
            float2 v0 = *reinterpret_cast<const float2*>(g_x + (size_t)s0 * H + f);
            float2 v1 = *reinterpret_cast<const float2*>(g_x + (size_t)s1 * H + f);
            a0.x += v0.x; a0.y += v0.y;
            a1.x += v1.x; a1.y += v1.y;
            i += 2;
        }
        if (i < deg) {
            int s0 = __ldg(g_adj + start + i);
            float2 v0 = *reinterpret_cast<const float2*>(g_x + (size_t)s0 * H + f);
            a0.x += v0.x; a0.y += v0.y;
        }
        float inv = 1.f / fmaxf((float)deg, 1.f);
        float sx = (a0.x + a1.x) + (a2.x + a3.x);
        float sy = (a0.y + a1.y) + (a2.y + a3.y);
        *reinterpret_cast<float2*>(g_agg + (size_t)node * H + f) =
            make_float2(sx * inv, sy * inv);
    }
}

// ---------------- layer-2 aggregation: persistent grid-stride, float1 x4 ------
__global__ void __launch_bounds__(256) aggregate32() {
    const int nwarps = (int)gridDim.x * 8;
    int gw = (blockIdx.x * 256 + threadIdx.x) >> 5;
    int lane = threadIdx.x & 31;
    for (int idx = gw; idx < NTOT; idx += nwarps) {
        int node = NTOT - 1 - idx;
        int start = g_rowstart[node];
        int deg = g_deg[node];
        float a0 = 0.f, a1 = 0.f, a2 = 0.f, a3 = 0.f;
        int i = 0;
        for (; i + 3 < deg; i += 4) {
            int s0 = __ldg(g_adj + start + i);
            int s1 = __ldg(g_adj + start + i + 1);
            int s2 = __ldg(g_adj + start + i + 2);
            int s3 = __ldg(g_adj + start + i + 3);
            a0 += __ldg(g_y + (size_t)s0 * O + lane);
            a1 += __ldg(g_y + (size_t)s1 * O + lane);
            a2 += __ldg(g_y + (size_t)s2 * O + lane);
            a3 += __ldg(g_y + (size_t)s3 * O + lane);
        }
        if (i + 1 < deg) {
            int s0 = __ldg(g_adj + start + i);
            int s1 = __ldg(g_adj + start + i + 1);
            a0 += __ldg(g_y + (size_t)s0 * O + lane);
            a1 += __ldg(g_y + (size_t)s1 * O + lane);
            i += 2;
        }
        if (i < deg) {
            int s0 = __ldg(g_adj + start + i);
            a0 += __ldg(g_y + (size_t)s0 * O + lane);
        }
        float inv = 1.f / fmaxf((float)deg, 1.f);
        g_aggy[(size_t)node * O + lane] = ((a0 + a1) + (a2 + a3)) * inv;
    }
}

// ---------------- SAGE finalize layer 1 (round-5 body) ------------------------
__global__ void __launch_bounds__(256) finalize1_tc(const float* __restrict__ Wr,
                                                    const float* __restrict__ Wl,
                                                    const float* __restrict__ bias) {
    __shared__ uint32_t As[128][20];
    __shared__ uint32_t Ws[64][20];
    const int tid = threadIdx.x;
    const int m0 = blockIdx.x * 128;
    const int warp = tid >> 5, lane = tid & 31;
    const int g = lane >> 2, t = lane & 3;

    float acc[8][4];
#pragma unroll
    for (int j = 0; j < 8; j++)
#pragma unroll
        for (int c = 0; c < 4; c++) acc[j][c] = 0.f;

    for (int kb = 0; kb < 2 * H; kb += 16) {
        const float* src = (kb < H) ? g_x : g_agg;
        const float* W = (kb < H) ? Wr : Wl;
        const int kcol = kb & (H - 1);
#pragma unroll
        for (int q = 0; q < 2; q++) {
            int idx = tid + 256 * q;
            int row = idx >> 2, c4 = idx & 3;
            int rg = m0 + row; if (rg > NTOT - 1) rg = NTOT - 1;
            float4 v = *reinterpret_cast<const float4*>(src + (size_t)rg * H + kcol + c4 * 4);
            uint4 u = make_uint4(f2tf(v.x), f2tf(v.y), f2tf(v.z), f2tf(v.w));
            *reinterpret_cast<uint4*>(&As[row][c4 * 4]) = u;
        }
        {
            int n = tid >> 2, c4 = tid & 3;
            float4 v = *reinterpret_cast<const float4*>(W + (size_t)n * H + kcol + c4 * 4);
            uint4 u = make_uint4(f2tf(v.x), f2tf(v.y), f2tf(v.z), f2tf(v.w));
            *reinterpret_cast<uint4*>(&Ws[n][c4 * 4]) = u;
        }
        __syncthreads();
        const int r0 = warp * 16;
#pragma unroll
        for (int ks = 0; ks < 2; ks++) {
            int k0 = ks * 8;
            uint32_t a0 = As[r0 + g][k0 + t];
            uint32_t a1 = As[r0 + g + 8][k0 + t];
            uint32_t a2 = As[r0 + g][k0 + t + 4];
            uint32_t a3 = As[r0 + g + 8][k0 + t + 4];
#pragma unroll
            for (int j = 0; j < 8; j++) {
                uint32_t b0 = Ws[j * 8 + g][k0 + t];
                uint32_t b1 = Ws[j * 8 + g][k0 + t + 4];
                mma_tf32(acc[j], a0, a1, a2, a3, b0, b1);
            }
        }
        __syncthreads();
    }
#pragma unroll
    for (int j = 0; j < 8; j++) {
        int col = j * 8 + 2 * t;
        float b0 = bias[col], b1 = bias[col + 1];
        int r1 = m0 + warp * 16 + g;
        if (r1 < NTOT) {
            float2 o = make_float2(fmaxf(acc[j][0] + b0, 0.f), fmaxf(acc[j][1] + b1, 0.f));
            *reinterpret_cast<float2*>(g_h + (size_t)r1 * H + col) = o;
        }
        int r2 = r1 + 8;
        if (r2 < NTOT) {
            float2 o = make_float2(fmaxf(acc[j][2] + b0, 0.f), fmaxf(acc[j][3] + b1, 0.f));
            *reinterpret_cast<float2*>(g_h + (size_t)r2 * H + col) = o;
        }
    }
}

// ---------------- y = h @ W2l^T (streaming GEMM, K=64, N=32) ------------------
__global__ void __launch_bounds__(256) y_tc(const float* __restrict__ W2l) {
    __shared__ uint32_t As[128][20];
    __shared__ uint32_t Ws[O][20];
    const int tid = threadIdx.x;
    const int m0 = blockIdx.x * 128;
    const int warp = tid >> 5, lane = tid & 31;
    const int g = lane >> 2, t = lane & 3;
    const int r0 = warp * 16;

    float acc[4][4];
#pragma unroll
    for (int j = 0; j < 4; j++)
#pragma unroll
        for (int c = 0; c < 4; c++) acc[j][c] = 0.f;

    for (int kb = 0; kb < H; kb += 16) {
#pragma unroll
        for (int q = 0; q < 2; q++) {
            int idx = tid + 256 * q;
            int row = idx >> 2, c4 = idx & 3;
            int rg = m0 + row; if (rg > NTOT - 1) rg = NTOT - 1;
            float4 v = *reinterpret_cast<const float4*>(g_h + (size_t)rg * H + kb + c4 * 4);
            uint4 u = make_uint4(f2tf(v.x), f2tf(v.y), f2tf(v.z), f2tf(v.w));
            *reinterpret_cast<uint4*>(&As[row][c4 * 4]) = u;
        }
        if (tid < O * 4) {
            int n = tid >> 2, c4 = tid & 3;
            float4 v = *reinterpret_cast<const float4*>(W2l + (size_t)n * H + kb + c4 * 4);
            uint4 u = make_uint4(f2tf(v.x), f2tf(v.y), f2tf(v.z), f2tf(v.w));
            *reinterpret_cast<uint4*>(&Ws[n][c4 * 4]) = u;
        }
        __syncthreads();
#pragma unroll
        for (int ks = 0; ks < 2; ks++) {
            int k0 = ks * 8;
            uint32_t a0 = As[r0 + g][k0 + t];
            uint32_t a1 = As[r0 + g + 8][k0 + t];
            uint32_t a2 = As[r0 + g][k0 + t + 4];
            uint32_t a3 = As[r0 + g + 8][k0 + t + 4];
#pragma unroll
            for (int j = 0; j < 4; j++) {
                uint32_t b0 = Ws[j * 8 + g][k0 + t];
                uint32_t b1 = Ws[j * 8 + g][k0 + t + 4];
                mma_tf32(acc[j], a0, a1, a2, a3, b0, b1);
            }
        }
        __syncthreads();
    }
#pragma unroll
    for (int j = 0; j < 4; j++) {
        int col = j * 8 + 2 * t;
        int r1 = m0 + r0 + g, r2 = r1 + 8;
        if (r1 < NTOT)
            *reinterpret_cast<float2*>(g_y + (size_t)r1 * O + col) =
                make_float2(acc[j][0], acc[j][1]);
        if (r2 < NTOT)
            *reinterpret_cast<float2*>(g_y + (size_t)r2 * O + col) =
                make_float2(acc[j][2], acc[j][3]);
    }
}

// ---------------- fin2: out = h@W2r^T + aggy + b2 (K=64, N=32) ----------------
__global__ void __launch_bounds__(256) fin2_tc(const float* __restrict__ W2r,
                                               const float* __restrict__ b2,
                                               float* __restrict__ out) {
    __shared__ uint32_t As[128][20];
    __shared__ uint32_t Ws[O][20];
    const int tid = threadIdx.x;
    const int m0 = blockIdx.x * 128;
    const int warp = tid >> 5, lane = tid & 31;
    const int g = lane >> 2, t = lane & 3;
    const int r0 = warp * 16;

    float acc[4][4];
#pragma unroll
    for (int j = 0; j < 4; j++)
#pragma unroll
        for (int c = 0; c < 4; c++) acc[j][c] = 0.f;

    for (int kb = 0; kb < H; kb += 16) {
#pragma unroll
        for (int q = 0; q < 2; q++) {
            int idx = tid + 256 * q;
            int row = idx >> 2, c4 = idx & 3;
            int rg = m0 + row; if (rg > NTOT - 1) rg = NTOT - 1;
            float4 v = *reinterpret_cast<const float4*>(g_h + (size_t)rg * H + kb + c4 * 4);
            uint4 u = make_uint4(f2tf(v.x), f2tf(v.y), f2tf(v.z), f2tf(v.w));
            *reinterpret_cast<uint4*>(&As[row][c4 * 4]) = u;
        }
        if (tid < O * 4) {
            int n = tid >> 2, c4 = tid & 3;
            float4 v = *reinterpret_cast<const float4*>(W2r + (size_t)n * H + kb + c4 * 4);
            uint4 u = make_uint4(f2tf(v.x), f2tf(v.y), f2tf(v.z), f2tf(v.w));
            *reinterpret_cast<uint4*>(&Ws[n][c4 * 4]) = u;
        }
        __syncthreads();
#pragma unroll
        for (int ks = 0; ks < 2; ks++) {
            int k0 = ks * 8;
            uint32_t a0 = As[r0 + g][k0 + t];
            uint32_t a1 = As[r0 + g + 8][k0 + t];
            uint32_t a2 = As[r0 + g][k0 + t + 4];
            uint32_t a3 = As[r0 + g + 8][k0 + t + 4];
#pragma unroll
            for (int j = 0; j < 4; j++) {
                uint32_t b0 = Ws[j * 8 + g][k0 + t];
                uint32_t b1 = Ws[j * 8 + g][k0 + t + 4];
                mma_tf32(acc[j], a0, a1, a2, a3, b0, b1);
            }
        }
        __syncthreads();
    }
#pragma unroll
    for (int j = 0; j < 4; j++) {
        int col = j * 8 + 2 * t;
        float b0 = b2[col], b1v = b2[col + 1];
        int r1 = m0 + r0 + g, r2 = r1 + 8;
        if (r1 < NTOT) {
            float2 ay = *reinterpret_cast<const float2*>(g_aggy + (size_t)r1 * O + col);
            *reinterpret_cast<float2*>(out + (size_t)r1 * O + col) =
                make_float2(acc[j][0] + b0 + ay.x, acc[j][1] + b1v + ay.y);
        }
        if (r2 < NTOT) {
            float2 ay = *reinterpret_cast<const float2*>(g_aggy + (size_t)r2 * O + col);
            *reinterpret_cast<float2*>(out + (size_t)r2 * O + col) =
                make_float2(acc[j][2] + b0 + ay.x, acc[j][3] + b1v + ay.y);
        }
    }
}

// ---------------- launch -------------------------------------------------------
extern "C" void kernel_launch(void* const* d_in, const int* in_sizes, int n_in,
                              void* d_out, int out_size) {
    const float* x_product = (const float*)d_in[0];
    const int* pb_src = (const int*)d_in[1];
    const int* pb_dst = (const int*)d_in[2];
    const int* pc_src = (const int*)d_in[3];
    const int* pc_dst = (const int*)d_in[4];
    const int* ps_src = (const int*)d_in[5];
    const int* ps_dst = (const int*)d_in[6];
    const float* W_proj = (const float*)d_in[7];
    const float* b_proj = (const float*)d_in[8];
    const float* emb_brand = (const float*)d_in[9];
    const float* emb_cat = (const float*)d_in[10];
    const float* emb_shop = (const float*)d_in[11];
    const float* W1_l = (const float*)d_in[12];
    const float* b1_l = (const float*)d_in[13];
    const float* W1_r = (const float*)d_in[14];
    const float* W2_l = (const float*)d_in[15];
    const float* b2_l = (const float*)d_in[16];
    const float* W2_r = (const float*)d_in[17];
    float* out = (float*)d_out;

    const int nodeBlocks = (NTOT + 255) / 256;
    const int edgeBlocks = (3 * NE + 255) / 256;
    const int gemmBlocks = (NTOT + 127) / 128;

    static cudaStream_t s2 = nullptr;
    static cudaEvent_t evFork = nullptr, evJoin = nullptr;
    if (!s2) {
        cudaStreamCreateWithFlags(&s2, cudaStreamNonBlocking);
        cudaEventCreateWithFlags(&evFork, cudaEventDisableTiming);
        cudaEventCreateWithFlags(&evJoin, cudaEventDisableTiming);
    }

    // fork: CSR build on s2, feature assembly on main (round-5 proven DAG)
    cudaEventRecord(evFork, 0);
    cudaStreamWaitEvent(s2, evFork, 0);

    zero_deg<<<nodeBlocks, 256, 0, s2>>>();
    hist_edges<<<edgeBlocks, 256, 0, s2>>>(pb_src, pb_dst, pc_src, pc_dst, ps_src, ps_dst);
    scanA<<<NBLK_SCAN, 256, 0, s2>>>();
    scanB<<<1, 512, 0, s2>>>();
    scanC<<<nodeBlocks, 256, 0, s2>>>();
    fill_csr<<<edgeBlocks, 256, 0, s2>>>(pb_src, pb_dst, pc_src, pc_dst, ps_src, ps_dst);
    cudaEventRecord(evJoin, s2);

    proj_tc<<<(NP + 127) / 128, 256>>>(x_product, W_proj, b_proj);
    copy_emb<<<((NB + NC + NS) * H / 4 + 255) / 256, 256>>>(emb_brand, emb_cat, emb_shop);

    cudaStreamWaitEvent(0, evJoin, 0);

    // --- layer 1 ---
    aggregate64<<<PERS_BLOCKS, 256>>>();
    finalize1_tc<<<gemmBlocks, 256>>>(W1_r, W1_l, b1_l);
    // --- y projection + layer 2 ---
    y_tc<<<gemmBlocks, 256>>>(W2_l);
    aggregate32<<<PERS_BLOCKS, 256>>>();
    fin2_tc<<<gemmBlocks, 256>>>(W2_r, b2_l, out);
}

// round 14
// speedup vs baseline: 1.0830x; 1.0445x over previous
#include <cuda_runtime.h>
#include <cstdint>

#define NP 500000
#define NB 20000
#define NC 5000
#define NS 2000
#define NTOT 527000
#define NE 500000
#define EDIR (3 * NE * 2)
#define H 64
#define O 32
#define FIN 384

#define SCAN_SPAN 2048
#define NBLK_SCAN ((NTOT + SCAN_SPAN - 1) / SCAN_SPAN)
#define PERS_BLOCKS 1184   // 148 SMs x 8 CTAs

// ---------------- scratch ----------------------------------------------------
__device__ float g_x[(size_t)NTOT * H];
__device__ float g_h[(size_t)NTOT * H];
__device__ float g_agg[(size_t)NTOT * H];    // layer-1 mean of x (64-dim)
__device__ float g_y[(size_t)NTOT * O];      // y = relu(h) @ W2_l^T (32-dim)
__device__ int   g_deg[NTOT];
__device__ int   g_rowstart[NTOT];
__device__ int   g_cursor[NTOT];
__device__ int   g_scaninc[NTOT];
__device__ int   g_blocksum[512];
__device__ int   g_adj[EDIR];

// ---------------- tf32 helpers ----------------------------------------------
__device__ __forceinline__ uint32_t f2tf(float x) {
    uint32_t r;
    asm("cvt.rna.tf32.f32 %0, %1;" : "=r"(r) : "f"(x));
    return r;
}
__device__ __forceinline__ void mma_tf32(float* d, uint32_t a0, uint32_t a1,
                                         uint32_t a2, uint32_t a3,
                                         uint32_t b0, uint32_t b1) {
    asm volatile(
        "mma.sync.aligned.m16n8k8.row.col.f32.tf32.tf32.f32 "
        "{%0,%1,%2,%3},{%4,%5,%6,%7},{%8,%9},{%0,%1,%2,%3};"
        : "+f"(d[0]), "+f"(d[1]), "+f"(d[2]), "+f"(d[3])
        : "r"(a0), "r"(a1), "r"(a2), "r"(a3), "r"(b0), "r"(b1));
}

// ---------------- CSR build ---------------------------------------------------
__global__ void __launch_bounds__(256) zero_deg() {
    int i = blockIdx.x * 256 + threadIdx.x;
    if (i < NTOT) g_deg[i] = 0;
}

__global__ void __launch_bounds__(256) hist_edges(
    const int* __restrict__ pb_src, const int* __restrict__ pb_dst,
    const int* __restrict__ pc_src, const int* __restrict__ pc_dst,
    const int* __restrict__ ps_src, const int* __restrict__ ps_dst) {
    int e = blockIdx.x * 256 + threadIdx.x;
    if (e >= 3 * NE) return;
    int t = e / NE, i = e - t * NE;
    const int* sp; const int* dp; int off;
    if (t == 0)      { sp = pb_src; dp = pb_dst; off = NP; }
    else if (t == 1) { sp = pc_src; dp = pc_dst; off = NP + NB; }
    else             { sp = ps_src; dp = ps_dst; off = NP + NB + NC; }
    int p = __ldg(sp + i);
    int o = __ldg(dp + i) + off;
    atomicAdd(&g_deg[p], 1);
    atomicAdd(&g_deg[o], 1);
}

__global__ void __launch_bounds__(256) scanA() {
    __shared__ int wsum[8];
    __shared__ int wpre[8];
    int tid = threadIdx.x, lane = tid & 31, wid = tid >> 5;
    int base = blockIdx.x * SCAN_SPAN + tid * 8;
    int v[8], run = 0;
#pragma unroll
    for (int t = 0; t < 8; t++) {
        int idx = base + t;
        int d = (idx < NTOT) ? g_deg[idx] : 0;
        run += d;
        v[t] = run;
    }
    int tot = run;
#pragma unroll
    for (int off = 1; off < 32; off <<= 1) {
        int n = __shfl_up_sync(0xffffffffu, tot, off);
        if (lane >= off) tot += n;
    }
    int wexcl = tot - run;
    if (lane == 31) wsum[wid] = tot;
    __syncthreads();
    if (tid < 8) {
        int s = wsum[tid];
        int r = s;
#pragma unroll
        for (int off = 1; off < 8; off <<= 1) {
            int n = __shfl_up_sync(0xffu, r, off);
            if (tid >= off) r += n;
        }
        wpre[tid] = r - s;
        if (tid == 7) g_blocksum[blockIdx.x] = r;
    }
    __syncthreads();
    int bexcl = wexcl + wpre[wid];
#pragma unroll
    for (int t = 0; t < 8; t++) {
        int idx = base + t;
        if (idx < NTOT) g_scaninc[idx] = v[t] + bexcl;
    }
}

__global__ void __launch_bounds__(512) scanB() {
    __shared__ int s[NBLK_SCAN];
    int tid = threadIdx.x;
    if (tid < NBLK_SCAN) s[tid] = g_blocksum[tid];
    __syncthreads();
    if (tid == 0) {
        int run = 0;
        for (int i = 0; i < NBLK_SCAN; i++) { int t = s[i]; s[i] = run; run += t; }
    }
    __syncthreads();
    if (tid < NBLK_SCAN) g_blocksum[tid] = s[tid];
}

__global__ void __launch_bounds__(256) scanC() {
    int i = blockIdx.x * 256 + threadIdx.x;
    if (i >= NTOT) return;
    int start = g_scaninc[i] + g_blocksum[i >> 11] - g_deg[i];
    g_rowstart[i] = start;
    g_cursor[i] = start;
}

__global__ void __launch_bounds__(256) fill_csr(
    const int* __restrict__ pb_src, const int* __restrict__ pb_dst,
    const int* __restrict__ pc_src, const int* __restrict__ pc_dst,
    const int* __restrict__ ps_src, const int* __restrict__ ps_dst) {
    int e = blockIdx.x * 256 + threadIdx.x;
    if (e >= 3 * NE) return;
    int t = e / NE, i = e - t * NE;
    const int* sp; const int* dp; int off;
    if (t == 0)      { sp = pb_src; dp = pb_dst; off = NP; }
    else if (t == 1) { sp = pc_src; dp = pc_dst; off = NP + NB; }
    else             { sp = ps_src; dp = ps_dst; off = NP + NB + NC; }
    int p = __ldg(sp + i);
    int o = __ldg(dp + i) + off;
    int pos = atomicAdd(&g_cursor[o], 1);
    g_adj[pos] = p;
    int pos2 = atomicAdd(&g_cursor[p], 1);
    g_adj[pos2] = o;
}

// ---------------- feature assembly --------------------------------------------
__global__ void __launch_bounds__(256) copy_emb(const float* __restrict__ eb,
                                                const float* __restrict__ ec,
                                                const float* __restrict__ es) {
    int i = blockIdx.x * 256 + threadIdx.x;
    const int tot = (NB + NC + NS) * H / 4;
    if (i >= tot) return;
    const int nb4 = NB * H / 4, nc4 = NC * H / 4;
    float4 v;
    if (i < nb4) v = reinterpret_cast<const float4*>(eb)[i];
    else if (i < nb4 + nc4) v = reinterpret_cast<const float4*>(ec)[i - nb4];
    else v = reinterpret_cast<const float4*>(es)[i - nb4 - nc4];
    reinterpret_cast<float4*>(g_x)[(size_t)NP * H / 4 + i] = v;
}

// ---------------- proj: relu(x_product @ W_proj^T + b), register-prefetched ---
__global__ void __launch_bounds__(256) proj_tc(const float* __restrict__ A,
                                               const float* __restrict__ W,
                                               const float* __restrict__ bias) {
    __shared__ uint32_t As[128][20];
    __shared__ uint32_t Ws[64][20];
    const int tid = threadIdx.x;
    const int m0 = blockIdx.x * 128;
    const int warp = tid >> 5, lane = tid & 31;
    const int g = lane >> 2, t = lane & 3;

    const int arow = tid >> 2, ac4 = tid & 3;
    int arg0 = m0 + arow;        if (arg0 > NP - 1) arg0 = NP - 1;
    int arg1 = m0 + arow + 64;   if (arg1 > NP - 1) arg1 = NP - 1;
    const int wn = tid >> 2, wc4 = tid & 3;

    float acc[8][4];
#pragma unroll
    for (int j = 0; j < 8; j++)
#pragma unroll
        for (int c = 0; c < 4; c++) acc[j][c] = 0.f;

    float4 pa0 = *reinterpret_cast<const float4*>(A + (size_t)arg0 * FIN + ac4 * 4);
    float4 pa1 = *reinterpret_cast<const float4*>(A + (size_t)arg1 * FIN + ac4 * 4);
    float4 pw  = *reinterpret_cast<const float4*>(W + (size_t)wn * FIN + wc4 * 4);

    for (int kb = 0; kb < FIN; kb += 16) {
        *reinterpret_cast<uint4*>(&As[arow][ac4 * 4]) =
            make_uint4(f2tf(pa0.x), f2tf(pa0.y), f2tf(pa0.z), f2tf(pa0.w));
        *reinterpret_cast<uint4*>(&As[arow + 64][ac4 * 4]) =
            make_uint4(f2tf(pa1.x), f2tf(pa1.y), f2tf(pa1.z), f2tf(pa1.w));
        *reinterpret_cast<uint4*>(&Ws[wn][wc4 * 4]) =
            make_uint4(f2tf(pw.x), f2tf(pw.y), f2tf(pw.z), f2tf(pw.w));
        __syncthreads();
        if (kb + 16 < FIN) {
            pa0 = *reinterpret_cast<const float4*>(A + (size_t)arg0 * FIN + kb + 16 + ac4 * 4);
            pa1 = *reinterpret_cast<const float4*>(A + (size_t)arg1 * FIN + kb + 16 + ac4 * 4);
            pw  = *reinterpret_cast<const float4*>(W + (size_t)wn * FIN + kb + 16 + wc4 * 4);
        }
        const int r0 = warp * 16;
#pragma unroll
        for (int ks = 0; ks < 2; ks++) {
            int k0 = ks * 8;
            uint32_t a0 = As[r0 + g][k0 + t];
            uint32_t a1 = As[r0 + g + 8][k0 + t];
            uint32_t a2 = As[r0 + g][k0 + t + 4];
            uint32_t a3 = As[r0 + g + 8][k0 + t + 4];
#pragma unroll
            for (int j = 0; j < 8; j++) {
                uint32_t b0 = Ws[j * 8 + g][k0 + t];
                uint32_t b1 = Ws[j * 8 + g][k0 + t + 4];
                mma_tf32(acc[j], a0, a1, a2, a3, b0, b1);
            }
        }
        __syncthreads();
    }
#pragma unroll
    for (int j = 0; j < 8; j++) {
        int col = j * 8 + 2 * t;
        float b0 = bias[col], b1 = bias[col + 1];
        int r1 = m0 + warp * 16 + g;
        if (r1 < NP) {
            float2 o = make_float2(fmaxf(acc[j][0] + b0, 0.f), fmaxf(acc[j][1] + b1, 0.f));
            *reinterpret_cast<float2*>(g_x + (size_t)r1 * H + col) = o;
        }
        int r2 = r1 + 8;
        if (r2 < NP) {
            float2 o = make_float2(fmaxf(acc[j][2] + b0, 0.f), fmaxf(acc[j][3] + b1, 0.f));
            *reinterpret_cast<float2*>(g_x + (size_t)r2 * H + col) = o;
        }
    }
}

// ---------------- layer-1 aggregation: persistent grid-stride, float2 x4 ------
__global__ void __launch_bounds__(256) aggregate64() {
    const int nwarps = (int)gridDim.x * 8;
    int gw = (blockIdx.x * 256 + threadIdx.x) >> 5;
    int lane = threadIdx.x & 31;
    int f = lane * 2;
    for (int idx = gw; idx < NTOT; idx += nwarps) {
        int node = NTOT - 1 - idx;   // heavy (high-id) rows first
        int start = g_rowstart[node];
        int deg = g_deg[node];
        float2 a0 = make_float2(0.f, 0.f), a1 = make_float2(0.f, 0.f);
        float2 a2 = make_float2(0.f, 0.f), a3 = make_float2(0.f, 0.f);
        int i = 0;
        for (; i + 3 < deg; i += 4) {
            int s0 = __ldg(g_adj + start + i);
            int s1 = __ldg(g_adj + start + i + 1);
            int s2 = __ldg(g_adj + start + i + 2);
            int s3 = __ldg(g_adj + start + i + 3);
            float2 v0 = *reinterpret_cast<const float2*>(g_x + (size_t)s0 * H + f);
            float2 v1 = *reinterpret_cast<const float2*>(g_x + (size_t)s1 * H + f);
            float2 v2 = *reinterpret_cast<const float2*>(g_x + (size_t)s2 * H + f);
            float2 v3 = *reinterpret_cast<const float2*>(g_x + (size_t)s3 * H + f);
            a0.x += v0.x; a0.y += v0.y;
            a1.x += v1.x; a1.y += v1.y;
            a2.x += v2.x; a2.y += v2.y;
            a3.x += v3.x; a3.y += v3.y;
        }
        if (i + 1 < deg) {
            int s0 = __ldg(g_adj + start + i);
            int s1 = __ldg(g_adj + start + i + 1);
            float2 v0 = *reinterpret_cast<const float2*>(g_x + (size_t)s0 * H + f);
            float2 v1 = *reinterpret_cast<const float2*>(g_x + (size_t)s1 * H + f);
            a0.x += v0.x; a0.y += v0.y;
            a1.x += v1.x; a1.y += v1.y;
            i += 2;
        }
        if (i < deg) {
            int s0 = __ldg(g_adj + start + i);
            float2 v0 = *reinterpret_cast<const float2*>(g_x + (size_t)s0 * H + f);
            a0.x += v0.x; a0.y += v0.y;
        }
        float inv = 1.f / fmaxf((float)deg, 1.f);
        float sx = (a0.x + a1.x) + (a2.x + a3.x);
        float sy = (a0.y + a1.y) + (a2.y + a3.y);
        *reinterpret_cast<float2*>(g_agg + (size_t)node * H + f) =
            make_float2(sx * inv, sy * inv);
    }
}

// ---------------- layer-2 aggregation: persistent; writes FINAL output --------
// out[node] = z[node] + mean_j y[j], where z = h@W2r^T + b2 (precomputed in out).
__global__ void __launch_bounds__(256) aggregate32(float* __restrict__ out) {
    const int nwarps = (int)gridDim.x * 8;
    int gw = (blockIdx.x * 256 + threadIdx.x) >> 5;
    int lane = threadIdx.x & 31;
    for (int idx = gw; idx < NTOT; idx += nwarps) {
        int node = NTOT - 1 - idx;
        int start = g_rowstart[node];
        int deg = g_deg[node];
        float a0 = 0.f, a1 = 0.f, a2 = 0.f, a3 = 0.f;
        int i = 0;
        for (; i + 3 < deg; i += 4) {
            int s0 = __ldg(g_adj + start + i);
            int s1 = __ldg(g_adj + start + i + 1);
            int s2 = __ldg(g_adj + start + i + 2);
            int s3 = __ldg(g_adj + start + i + 3);
            a0 += __ldg(g_y + (size_t)s0 * O + lane);
            a1 += __ldg(g_y + (size_t)s1 * O + lane);
            a2 += __ldg(g_y + (size_t)s2 * O + lane);
            a3 += __ldg(g_y + (size_t)s3 * O + lane);
        }
        if (i + 1 < deg) {
            int s0 = __ldg(g_adj + start + i);
            int s1 = __ldg(g_adj + start + i + 1);
            a0 += __ldg(g_y + (size_t)s0 * O + lane);
            a1 += __ldg(g_y + (size_t)s1 * O + lane);
            i += 2;
        }
        if (i < deg) {
            int s0 = __ldg(g_adj + start + i);
            a0 += __ldg(g_y + (size_t)s0 * O + lane);
        }
        float inv = 1.f / fmaxf((float)deg, 1.f);
        size_t off = (size_t)node * O + lane;
        out[off] = out[off] + ((a0 + a1) + (a2 + a3)) * inv;
    }
}

// ---------------- finalize layer 1, register-prefetched -----------------------
// h = relu(x@W1r^T + agg@W1l^T + b1) -> g_h. Virtual K=128.
__global__ void __launch_bounds__(256) finalize1_tc(const float* __restrict__ Wr,
                                                    const float* __restrict__ Wl,
                                                    const float* __restrict__ bias) {
    __shared__ uint32_t As[128][20];
    __shared__ uint32_t Ws[64][20];
    const int tid = threadIdx.x;
    const int m0 = blockIdx.x * 128;
    const int warp = tid >> 5, lane = tid & 31;
    const int g = lane >> 2, t = lane & 3;

    const int arow = tid >> 2, ac4 = tid & 3;
    int arg0 = m0 + arow;        if (arg0 > NTOT - 1) arg0 = NTOT - 1;
    int arg1 = m0 + arow + 64;   if (arg1 > NTOT - 1) arg1 = NTOT - 1;
    const int wn = tid >> 2, wc4 = tid & 3;

    float acc[8][4];
#pragma unroll
    for (int j = 0; j < 8; j++)
#pragma unroll
        for (int c = 0; c < 4; c++) acc[j][c] = 0.f;

    float4 pa0 = *reinterpret_cast<const float4*>(g_x + (size_t)arg0 * H + ac4 * 4);
    float4 pa1 = *reinterpret_cast<const float4*>(g_x + (size_t)arg1 * H + ac4 * 4);
    float4 pw  = *reinterpret_cast<const float4*>(Wr + (size_t)wn * H + wc4 * 4);

    for (int kb = 0; kb < 2 * H; kb += 16) {
        *reinterpret_cast<uint4*>(&As[arow][ac4 * 4]) =
            make_uint4(f2tf(pa0.x), f2tf(pa0.y), f2tf(pa0.z), f2tf(pa0.w));
        *reinterpret_cast<uint4*>(&As[arow + 64][ac4 * 4]) =
            make_uint4(f2tf(pa1.x), f2tf(pa1.y), f2tf(pa1.z), f2tf(pa1.w));
        *reinterpret_cast<uint4*>(&Ws[wn][wc4 * 4]) =
            make_uint4(f2tf(pw.x), f2tf(pw.y), f2tf(pw.z), f2tf(pw.w));
        __syncthreads();
        if (kb + 16 < 2 * H) {
            int nb = kb + 16;
            int kcol = nb & (H - 1);
            const float* src = (nb < H) ? g_x : g_agg;
            const float* W = (nb < H) ? Wr : Wl;
            pa0 = *reinterpret_cast<const float4*>(src + (size_t)arg0 * H + kcol + ac4 * 4);
            pa1 = *reinterpret_cast<const float4*>(src + (size_t)arg1 * H + kcol + ac4 * 4);
            pw  = *reinterpret_cast<const float4*>(W + (size_t)wn * H + kcol + wc4 * 4);
        }
        const int r0 = warp * 16;
#pragma unroll
        for (int ks = 0; ks < 2; ks++) {
            int k0 = ks * 8;
            uint32_t a0 = As[r0 + g][k0 + t];
            uint32_t a1 = As[r0 + g + 8][k0 + t];
            uint32_t a2 = As[r0 + g][k0 + t + 4];
            uint32_t a3 = As[r0 + g + 8][k0 + t + 4];
#pragma unroll
            for (int j = 0; j < 8; j++) {
                uint32_t b0 = Ws[j * 8 + g][k0 + t];
                uint32_t b1 = Ws[j * 8 + g][k0 + t + 4];
                mma_tf32(acc[j], a0, a1, a2, a3, b0, b1);
            }
        }
        __syncthreads();
    }
#pragma unroll
    for (int j = 0; j < 8; j++) {
        int col = j * 8 + 2 * t;
        float b0 = bias[col], b1 = bias[col + 1];
        int r1 = m0 + warp * 16 + g;
        if (r1 < NTOT) {
            float2 o = make_float2(fmaxf(acc[j][0] + b0, 0.f), fmaxf(acc[j][1] + b1, 0.f));
            *reinterpret_cast<float2*>(g_h + (size_t)r1 * H + col) = o;
        }
        int r2 = r1 + 8;
        if (r2 < NTOT) {
            float2 o = make_float2(fmaxf(acc[j][2] + b0, 0.f), fmaxf(acc[j][3] + b1, 0.f));
            *reinterpret_cast<float2*>(g_h + (size_t)r2 * H + col) = o;
        }
    }
}

// ---------------- yz: one pass over h computes y = h@W2l^T and z = h@W2r^T+b2 -
// Combined N=64 output (cols 0..31 -> g_y, cols 32..63 -> out with bias).
__global__ void __launch_bounds__(256) yz_tc(const float* __restrict__ W2l,
                                             const float* __restrict__ W2r,
                                             const float* __restrict__ b2,
                                             float* __restrict__ out) {
    __shared__ uint32_t As[128][20];
    __shared__ uint32_t Ws[64][20];
    const int tid = threadIdx.x;
    const int m0 = blockIdx.x * 128;
    const int warp = tid >> 5, lane = tid & 31;
    const int g = lane >> 2, t = lane & 3;
    const int r0 = warp * 16;

    float acc[8][4];
#pragma unroll
    for (int j = 0; j < 8; j++)
#pragma unroll
        for (int c = 0; c < 4; c++) acc[j][c] = 0.f;

    for (int kb = 0; kb < H; kb += 16) {
#pragma unroll
        for (int q = 0; q < 2; q++) {
            int idx = tid + 256 * q;
            int row = idx >> 2, c4 = idx & 3;
            int rg = m0 + row; if (rg > NTOT - 1) rg = NTOT - 1;
            float4 v = *reinterpret_cast<const float4*>(g_h + (size_t)rg * H + kb + c4 * 4);
            uint4 u = make_uint4(f2tf(v.x), f2tf(v.y), f2tf(v.z), f2tf(v.w));
            *reinterpret_cast<uint4*>(&As[row][c4 * 4]) = u;
        }
        {
            int n = tid >> 2, c4 = tid & 3;  // n 0..63: rows 0-31 = W2l, 32-63 = W2r
            const float* W = (n < 32) ? (W2l + (size_t)n * H) : (W2r + (size_t)(n - 32) * H);
            float4 v = *reinterpret_cast<const float4*>(W + kb + c4 * 4);
            uint4 u = make_uint4(f2tf(v.x), f2tf(v.y), f2tf(v.z), f2tf(v.w));
            *reinterpret_cast<uint4*>(&Ws[n][c4 * 4]) = u;
        }
        __syncthreads();
#pragma unroll
        for (int ks = 0; ks < 2; ks++) {
            int k0 = ks * 8;
            uint32_t a0 = As[r0 + g][k0 + t];
            uint32_t a1 = As[r0 + g + 8][k0 + t];
            uint32_t a2 = As[r0 + g][k0 + t + 4];
            uint32_t a3 = As[r0 + g + 8][k0 + t + 4];
#pragma unroll
            for (int j = 0; j < 8; j++) {
                uint32_t b0 = Ws[j * 8 + g][k0 + t];
                uint32_t b1 = Ws[j * 8 + g][k0 + t + 4];
                mma_tf32(acc[j], a0, a1, a2, a3, b0, b1);
            }
        }
        __syncthreads();
    }
#pragma unroll
    for (int j = 0; j < 8; j++) {
        int col = j * 8 + 2 * t;            // 0..63
        int r1 = m0 + r0 + g, r2 = r1 + 8;
        if (col < O) {                      // y columns
            if (r1 < NTOT)
                *reinterpret_cast<float2*>(g_y + (size_t)r1 * O + col) =
                    make_float2(acc[j][0], acc[j][1]);
            if (r2 < NTOT)
                *reinterpret_cast<float2*>(g_y + (size_t)r2 * O + col) =
                    make_float2(acc[j][2], acc[j][3]);
        } else {                            // z columns -> out (pre-aggregation)
            int zc = col - O;
            float b0 = b2[zc], b1v = b2[zc + 1];
            if (r1 < NTOT)
                *reinterpret_cast<float2*>(out + (size_t)r1 * O + zc) =
                    make_float2(acc[j][0] + b0, acc[j][1] + b1v);
            if (r2 < NTOT)
                *reinterpret_cast<float2*>(out + (size_t)r2 * O + zc) =
                    make_float2(acc[j][2] + b0, acc[j][3] + b1v);
        }
    }
}

// ---------------- launch -------------------------------------------------------
extern "C" void kernel_launch(void* const* d_in, const int* in_sizes, int n_in,
                              void* d_out, int out_size) {
    const float* x_product = (const float*)d_in[0];
    const int* pb_src = (const int*)d_in[1];
    const int* pb_dst = (const int*)d_in[2];
    const int* pc_src = (const int*)d_in[3];
    const int* pc_dst = (const int*)d_in[4];
    const int* ps_src = (const int*)d_in[5];
    const int* ps_dst = (const int*)d_in[6];
    const float* W_proj = (const float*)d_in[7];
    const float* b_proj = (const float*)d_in[8];
    const float* emb_brand = (const float*)d_in[9];
    const float* emb_cat = (const float*)d_in[10];
    const float* emb_shop = (const float*)d_in[11];
    const float* W1_l = (const float*)d_in[12];
    const float* b1_l = (const float*)d_in[13];
    const float* W1_r = (const float*)d_in[14];
    const float* W2_l = (const float*)d_in[15];
    const float* b2_l = (const float*)d_in[16];
    const float* W2_r = (const float*)d_in[17];
    float* out = (float*)d_out;

    const int nodeBlocks = (NTOT + 255) / 256;
    const int edgeBlocks = (3 * NE + 255) / 256;
    const int gemmBlocks = (NTOT + 127) / 128;

    static cudaStream_t s2 = nullptr;
    static cudaEvent_t evFork = nullptr, evJoin = nullptr;
    if (!s2) {
        cudaStreamCreateWithFlags(&s2, cudaStreamNonBlocking);
        cudaEventCreateWithFlags(&evFork, cudaEventDisableTiming);
        cudaEventCreateWithFlags(&evJoin, cudaEventDisableTiming);
    }

    // fork: CSR build on s2, feature assembly on main (proven DAG)
    cudaEventRecord(evFork, 0);
    cudaStreamWaitEvent(s2, evFork, 0);

    zero_deg<<<nodeBlocks, 256, 0, s2>>>();
    hist_edges<<<edgeBlocks, 256, 0, s2>>>(pb_src, pb_dst, pc_src, pc_dst, ps_src, ps_dst);
    scanA<<<NBLK_SCAN, 256, 0, s2>>>();
    scanB<<<1, 512, 0, s2>>>();
    scanC<<<nodeBlocks, 256, 0, s2>>>();
    fill_csr<<<edgeBlocks, 256, 0, s2>>>(pb_src, pb_dst, pc_src, pc_dst, ps_src, ps_dst);
    cudaEventRecord(evJoin, s2);

    proj_tc<<<(NP + 127) / 128, 256>>>(x_product, W_proj, b_proj);
    copy_emb<<<((NB + NC + NS) * H / 4 + 255) / 256, 256>>>(emb_brand, emb_cat, emb_shop);

    cudaStreamWaitEvent(0, evJoin, 0);

    // --- layer 1 ---
    aggregate64<<<PERS_BLOCKS, 256>>>();
    finalize1_tc<<<gemmBlocks, 256>>>(W1_r, W1_l, b1_l);
    // --- layer 2: one h pass computes y and z; aggregation finishes out ---
    yz_tc<<<gemmBlocks, 256>>>(W2_l, W2_r, b2_l, out);
    aggregate32<<<PERS_BLOCKS, 256>>>(out);
}